// round 10
// baseline (speedup 1.0000x reference)
#include <cuda_runtime.h>
#include <cstdint>

// LIF-MC-Refrac hybrid (R10) = R8 +
//  mma role: two-plane smem layout (8-k planes, 32B rows) ->
//    conflict-free STS.64 fill + conflict-free LDS.64 fragments.
//  Coupling role byte-identical to R8.

namespace {
constexpr int Bd = 4096;
constexpr int Hd = 2048;
constexpr int Kd = 2048;

constexpr int BM = 128, BN = 128, BK = 16;
constexpr int NTHREADS = 256;
constexpr int AST = BM + 4;           // coupling smem row stride (132 words)
constexpr int PLW = 1024;             // mma plane stride in words (128 rows x 8)

constexpr float DT_TAU_MEM = 0.1f;
constexpr float DT_TAU_SYN = 0.2f;
constexpr float V_TH_C     = 1.0f;
constexpr float RHO_RST    = 5.0f;

// coupling: 2*16*132*4 = 16896 ; mma: 4 planes * 1024 words * 4 = 16384
constexpr int SMEM_BYTES = 2 * BK * AST * 4;      // 16896
}

// ---- packed f32x2 helpers ----
__device__ __forceinline__ unsigned long long packf2(float lo, float hi) {
    unsigned long long r;
    asm("mov.b64 %0, {%1, %2};" : "=l"(r) : "f"(lo), "f"(hi));
    return r;
}
__device__ __forceinline__ unsigned long long dupf2(float x) {
    unsigned long long r;
    asm("mov.b64 %0, {%1, %1};" : "=l"(r) : "f"(x));
    return r;
}
__device__ __forceinline__ void ffma2(unsigned long long& d,
                                      unsigned long long a, unsigned long long b) {
    asm("fma.rn.f32x2 %0, %1, %2, %0;" : "+l"(d) : "l"(a), "l"(b));
}
__device__ __forceinline__ void unpackf2(unsigned long long v, float& lo, float& hi) {
    asm("mov.b64 {%0, %1}, %2;" : "=f"(lo), "=f"(hi) : "l"(v));
}

__device__ __forceinline__ void mma_tf32(float& c0, float& c1, float& c2, float& c3,
                                         uint32_t a0, uint32_t a1, uint32_t a2, uint32_t a3,
                                         uint32_t b0, uint32_t b1)
{
    asm volatile(
        "mma.sync.aligned.m16n8k8.row.col.f32.tf32.tf32.f32 "
        "{%0,%1,%2,%3},{%4,%5,%6,%7},{%8,%9},{%0,%1,%2,%3};"
        : "+f"(c0), "+f"(c1), "+f"(c2), "+f"(c3)
        : "r"(a0), "r"(a1), "r"(a2), "r"(a3), "r"(b0), "r"(b1));
}

__device__ __forceinline__ void lif_elem(float v, float i, float rho, float couple,
                                         float& z_out, float& v_out, float& rho_out)
{
    float dv    = DT_TAU_MEM * ((0.0f - v) + i);
    float v_dec = (v + dv) + couple;
    float z     = (v_dec - V_TH_C) > 0.0f ? 1.0f : 0.0f;
    float v_new = (1.0f - z) * v_dec;
    float mask  = rho > 0.0f ? 1.0f : 0.0f;
    v_new = (1.0f - mask) * v_new + mask * v;
    z     = (1.0f - mask) * z;
    rho_out = (1.0f - z) * fmaxf(rho - mask, 0.0f) + z * RHO_RST;
    z_out = z;
    v_out = v_new;
}

// ---------------- role 0: packed-fp32 coupling GEMM (R8, unchanged) ----------
__device__ void coupling_simt(
    char* smem_raw, int bx, int by,
    const float* __restrict__ A0, const float* __restrict__ W0,
    const float* __restrict__ vin, const float* __restrict__ iin,
    const float* __restrict__ rhoin,
    float* __restrict__ out_z, float* __restrict__ out_v, float* __restrict__ out_rho)
{
    float* As = (float*)smem_raw;                 // [BK][AST]
    float* Bs = As + BK * AST;                    // [BK][AST]

    const int tid = threadIdx.x;
    const int tx = tid & 15;
    const int ty = tid >> 4;
    const int cA = tx * 4;
    const int cB = 64 + tx * 4;

    const int loadRow = tid >> 2;
    const int loadK   = (tid & 3) << 2;

    unsigned long long acc2[4][8];
#pragma unroll
    for (int a = 0; a < 4; ++a)
#pragma unroll
        for (int b = 0; b < 8; ++b) acc2[a][b] = 0ull;

    const float* aPtr = A0 + (size_t)(by * BM + loadRow) * Kd + loadK;
    const float* wPtr = W0 + (size_t)(bx * BN + loadRow) * Kd + loadK;

    float4 ra0 = *(const float4*)(aPtr);
    float4 ra1 = *(const float4*)(aPtr + (size_t)64 * Kd);
    float4 rb0 = *(const float4*)(wPtr);
    float4 rb1 = *(const float4*)(wPtr + (size_t)64 * Kd);

    for (int kt = 0; kt < Kd; kt += BK) {
        __syncthreads();
        As[(loadK + 0) * AST + loadRow]      = ra0.x;
        As[(loadK + 1) * AST + loadRow]      = ra0.y;
        As[(loadK + 2) * AST + loadRow]      = ra0.z;
        As[(loadK + 3) * AST + loadRow]      = ra0.w;
        As[(loadK + 0) * AST + loadRow + 64] = ra1.x;
        As[(loadK + 1) * AST + loadRow + 64] = ra1.y;
        As[(loadK + 2) * AST + loadRow + 64] = ra1.z;
        As[(loadK + 3) * AST + loadRow + 64] = ra1.w;
        Bs[(loadK + 0) * AST + loadRow]      = rb0.x;
        Bs[(loadK + 1) * AST + loadRow]      = rb0.y;
        Bs[(loadK + 2) * AST + loadRow]      = rb0.z;
        Bs[(loadK + 3) * AST + loadRow]      = rb0.w;
        Bs[(loadK + 0) * AST + loadRow + 64] = rb1.x;
        Bs[(loadK + 1) * AST + loadRow + 64] = rb1.y;
        Bs[(loadK + 2) * AST + loadRow + 64] = rb1.z;
        Bs[(loadK + 3) * AST + loadRow + 64] = rb1.w;
        __syncthreads();

        if (kt + BK < Kd) {
            aPtr += BK; wPtr += BK;
            ra0 = *(const float4*)(aPtr);
            ra1 = *(const float4*)(aPtr + (size_t)64 * Kd);
            rb0 = *(const float4*)(wPtr);
            rb1 = *(const float4*)(wPtr + (size_t)64 * Kd);
        }

#pragma unroll
        for (int k = 0; k < BK; ++k) {
            float4 a0 = *(const float4*)&As[k * AST + ty * 8];
            float4 a1 = *(const float4*)&As[k * AST + ty * 8 + 4];
            float4 b0 = *(const float4*)&Bs[k * AST + cA];
            float4 b1 = *(const float4*)&Bs[k * AST + cB];

            unsigned long long ap[4];
            ap[0] = packf2(a0.x, a0.y);
            ap[1] = packf2(a0.z, a0.w);
            ap[2] = packf2(a1.x, a1.y);
            ap[3] = packf2(a1.z, a1.w);

            float bf[8] = {b0.x, b0.y, b0.z, b0.w, b1.x, b1.y, b1.z, b1.w};
#pragma unroll
            for (int b = 0; b < 8; ++b) {
                unsigned long long bb = dupf2(bf[b]);
                ffma2(acc2[0][b], ap[0], bb);
                ffma2(acc2[1][b], ap[1], bb);
                ffma2(acc2[2][b], ap[2], bb);
                ffma2(acc2[3][b], ap[3], bb);
            }
        }
    }

    float acc[8][8];
#pragma unroll
    for (int p = 0; p < 4; ++p)
#pragma unroll
        for (int b = 0; b < 8; ++b)
            unpackf2(acc2[p][b], acc[2 * p][b], acc[2 * p + 1][b]);

    const int row0 = by * BM + ty * 8;
    const int colA = bx * BN + cA;
    const int colB = bx * BN + cB;
#pragma unroll
    for (int a = 0; a < 8; ++a) {
#pragma unroll
        for (int h = 0; h < 2; ++h) {
            const size_t base = (size_t)(row0 + a) * Hd + (h ? colB : colA);
            const int boff = h * 4;
            float4 vv = *(const float4*)(vin + base);
            float4 iv = *(const float4*)(iin + base);
            float4 rv = *(const float4*)(rhoin + base);
            float4 oz, ov, orh;
            lif_elem(vv.x, iv.x, rv.x, acc[a][boff + 0], oz.x, ov.x, orh.x);
            lif_elem(vv.y, iv.y, rv.y, acc[a][boff + 1], oz.y, ov.y, orh.y);
            lif_elem(vv.z, iv.z, rv.z, acc[a][boff + 2], oz.z, ov.z, orh.z);
            lif_elem(vv.w, iv.w, rv.w, acc[a][boff + 3], oz.w, ov.w, orh.w);
            *(float4*)(out_z   + base) = oz;
            *(float4*)(out_v   + base) = ov;
            *(float4*)(out_rho + base) = orh;
        }
    }
}

// ---------------- role 1: TF32 MMA i-path, two-plane smem layout --------------
// Plane ks (0/1) holds k in [ks*8, ks*8+8): word(row, k) = row*8 + 2*(k&3) + ((k>>2)&1).
// Fragment uint2 at row*8 + 2q = (k=ks*8+q, k=ks*8+q+4)  -> conflict-free LDS.64.
// Loader thread t (=tid&3) loads k = {t, t+4, t+8, t+12}: plane-0 pair (t, t+4)
// and plane-1 pair (t+8, t+12) are each ONE float2 store -> conflict-free STS.64.
__device__ void ipath_mma(
    char* smem_raw, int bx, int by,
    const float* __restrict__ A0, const float* __restrict__ W0,
    const float* __restrict__ A1, const float* __restrict__ W1,
    const float* __restrict__ iin, float* __restrict__ out_i)
{
    uint32_t* Ap = (uint32_t*)smem_raw;           // 2 planes x 1024 words
    uint32_t* Bp = Ap + 2 * PLW;                  // 2 planes x 1024 words

    const int tid  = threadIdx.x;
    const int warp = tid >> 5;
    const int lane = tid & 31;
    const int g    = lane >> 2;
    const int q    = lane & 3;
    const int wM   = warp >> 2;
    const int wN   = warp & 3;

    const int loadRow = tid >> 2;   // 0..63 (also handles loadRow+64)
    const int t       = tid & 3;

    float acc[4][4][4];
#pragma unroll
    for (int mt = 0; mt < 4; ++mt)
#pragma unroll
        for (int nt = 0; nt < 4; ++nt)
#pragma unroll
            for (int r = 0; r < 4; ++r) acc[mt][nt][r] = 0.0f;

#pragma unroll
    for (int p = 0; p < 2; ++p) {
        const float* Am = (p == 0) ? A0 : A1;
        const float* Wm = (p == 0) ? W0 : W1;
        const float* aR0 = Am + (size_t)(by * BM + loadRow) * Kd + t;
        const float* aR1 = aR0 + (size_t)64 * Kd;
        const float* wR0 = Wm + (size_t)(bx * BN + loadRow) * Kd + t;
        const float* wR1 = wR0 + (size_t)64 * Kd;

        // prefetch first tile: k = t + {0,4,8,12}
        float a00 = aR0[0], a01 = aR0[4], a02 = aR0[8],  a03 = aR0[12];
        float a10 = aR1[0], a11 = aR1[4], a12 = aR1[8],  a13 = aR1[12];
        float b00 = wR0[0], b01 = wR0[4], b02 = wR0[8],  b03 = wR0[12];
        float b10 = wR1[0], b11 = wR1[4], b12 = wR1[8],  b13 = wR1[12];

        for (int kt = 0; kt < Kd; kt += BK) {
            __syncthreads();
            {
                const int w0 = loadRow * 8 + 2 * t;
                const int w1 = (loadRow + 64) * 8 + 2 * t;
                *(float2*)&Ap[w0]        = make_float2(a00, a01);  // plane 0
                *(float2*)&Ap[PLW + w0]  = make_float2(a02, a03);  // plane 1
                *(float2*)&Ap[w1]        = make_float2(a10, a11);
                *(float2*)&Ap[PLW + w1]  = make_float2(a12, a13);
                *(float2*)&Bp[w0]        = make_float2(b00, b01);
                *(float2*)&Bp[PLW + w0]  = make_float2(b02, b03);
                *(float2*)&Bp[w1]        = make_float2(b10, b11);
                *(float2*)&Bp[PLW + w1]  = make_float2(b12, b13);
            }
            __syncthreads();

            if (kt + BK < Kd) {
                aR0 += BK; aR1 += BK; wR0 += BK; wR1 += BK;
                a00 = aR0[0]; a01 = aR0[4]; a02 = aR0[8];  a03 = aR0[12];
                a10 = aR1[0]; a11 = aR1[4]; a12 = aR1[8];  a13 = aR1[12];
                b00 = wR0[0]; b01 = wR0[4]; b02 = wR0[8];  b03 = wR0[12];
                b10 = wR1[0]; b11 = wR1[4]; b12 = wR1[8];  b13 = wR1[12];
            }

#pragma unroll
            for (int ks = 0; ks < 2; ++ks) {
                const int pl = ks * PLW;
                uint2 bfr[4];
#pragma unroll
                for (int nt = 0; nt < 4; ++nt)
                    bfr[nt] = *(const uint2*)&Bp[pl + (wN * 32 + nt * 8 + g) * 8 + 2 * q];
#pragma unroll
                for (int mt = 0; mt < 4; ++mt) {
                    const int r0 = wM * 64 + mt * 16 + g;
                    uint2 ta = *(const uint2*)&Ap[pl + r0 * 8 + 2 * q];
                    uint2 tb = *(const uint2*)&Ap[pl + (r0 + 8) * 8 + 2 * q];
#pragma unroll
                    for (int nt = 0; nt < 4; ++nt) {
                        float* c = acc[mt][nt];
                        mma_tf32(c[0], c[1], c[2], c[3],
                                 ta.x, tb.x, ta.y, tb.y, bfr[nt].x, bfr[nt].y);
                    }
                }
            }
        }
    }

#pragma unroll
    for (int mt = 0; mt < 4; ++mt) {
#pragma unroll
        for (int nt = 0; nt < 4; ++nt) {
            const float* c = acc[mt][nt];
            int row0 = by * BM + wM * 64 + mt * 16 + g;
            int col  = bx * BN + wN * 32 + nt * 8 + 2 * q;
            size_t idx0 = (size_t)row0 * Hd + col;
            size_t idx1 = idx0 + (size_t)8 * Hd;
            float2 i0 = *(const float2*)(iin + idx0);
            float2 i1 = *(const float2*)(iin + idx1);
            float2 o0, o1;
            o0.x = (i0.x - DT_TAU_SYN * i0.x) + c[0];
            o0.y = (i0.y - DT_TAU_SYN * i0.y) + c[1];
            o1.x = (i1.x - DT_TAU_SYN * i1.x) + c[2];
            o1.y = (i1.y - DT_TAU_SYN * i1.y) + c[3];
            *(float2*)(out_i + idx0) = o0;
            *(float2*)(out_i + idx1) = o1;
        }
    }
}

__global__ void __launch_bounds__(NTHREADS, 2) lif_hybrid_kernel(
    const float* __restrict__ inp, const float* __restrict__ z,
    const float* __restrict__ v,   const float* __restrict__ icur,
    const float* __restrict__ rho,
    const float* __restrict__ Wi,  const float* __restrict__ Wr,
    const float* __restrict__ g,
    float* __restrict__ out_z, float* __restrict__ out_v,
    float* __restrict__ out_i, float* __restrict__ out_rho)
{
    __shared__ __align__(16) char smem_raw[SMEM_BYTES];

    const int bid  = blockIdx.x;
    const int role = (bid >> 2) & 1;     // co-resident CTAs mix roles
    const int sub  = (bid >> 3) * 4 + (bid & 3);
    const int bx = sub & 15;
    const int by = sub >> 4;

    if (role == 0) {
        coupling_simt(smem_raw, bx, by, v, g, v, icur, rho, out_z, out_v, out_rho);
    } else {
        ipath_mma(smem_raw, bx, by, inp, Wi, z, Wr, icur, out_i);
    }
}

extern "C" void kernel_launch(void* const* d_in, const int* in_sizes, int n_in,
                              void* d_out, int out_size)
{
    const float* inp  = (const float*)d_in[0];
    const float* z    = (const float*)d_in[1];
    const float* v    = (const float*)d_in[2];
    const float* icur = (const float*)d_in[3];
    const float* rho  = (const float*)d_in[4];
    const float* Wi   = (const float*)d_in[5];
    const float* Wr   = (const float*)d_in[6];
    const float* g    = (const float*)d_in[7];

    float* out      = (float*)d_out;
    const size_t nBH = (size_t)Bd * Hd;

    lif_hybrid_kernel<<<1024, NTHREADS>>>(
        inp, z, v, icur, rho, Wi, Wr, g,
        out, out + nBH, out + 2 * nBH, out + 3 * nBH);
}

// round 11
// speedup vs baseline: 1.1843x; 1.1843x over previous
#include <cuda_runtime.h>
#include <cstdint>

// LIF-MC-Refrac hybrid (R11) = R8 + conflict-free fills:
//  - coupling: store/load column XOR (k&8) -> STS.32 fill hits 32 distinct banks
//  - mma: new k-position map pos(k)=2f(a,c)+b (f0=[0,2,1,3], f1=[5,7,4,6]) ->
//    conflict-free scattered fill, fragments stay 2-wf optimal LDS.64
// All FP math and global access patterns byte-identical to R8.

namespace {
constexpr int Bd = 4096;
constexpr int Hd = 2048;
constexpr int Kd = 2048;

constexpr int BM = 128, BN = 128, BK = 16;
constexpr int NTHREADS = 256;
constexpr int SSTR = BK + 4;          // mma smem row stride (20 words)
constexpr int AST  = BM + 4;          // coupling smem row stride (132 words)

constexpr float DT_TAU_MEM = 0.1f;
constexpr float DT_TAU_SYN = 0.2f;
constexpr float V_TH_C     = 1.0f;
constexpr float RHO_RST    = 5.0f;

constexpr int SMEM_BYTES = 2 * BK * AST * 4;      // 16896 >= mma 20480? no:
// mma needs 2*128*20*4 = 20480 -> take max
constexpr int SMEM_BYTES_MAX = 2 * 128 * SSTR * 4; // 20480
}

// ---- packed f32x2 helpers ----
__device__ __forceinline__ unsigned long long packf2(float lo, float hi) {
    unsigned long long r;
    asm("mov.b64 %0, {%1, %2};" : "=l"(r) : "f"(lo), "f"(hi));
    return r;
}
__device__ __forceinline__ unsigned long long dupf2(float x) {
    unsigned long long r;
    asm("mov.b64 %0, {%1, %1};" : "=l"(r) : "f"(x));
    return r;
}
__device__ __forceinline__ void ffma2(unsigned long long& d,
                                      unsigned long long a, unsigned long long b) {
    asm("fma.rn.f32x2 %0, %1, %2, %0;" : "+l"(d) : "l"(a), "l"(b));
}
__device__ __forceinline__ void unpackf2(unsigned long long v, float& lo, float& hi) {
    asm("mov.b64 {%0, %1}, %2;" : "=f"(lo), "=f"(hi) : "l"(v));
}

__device__ __forceinline__ void mma_tf32(float& c0, float& c1, float& c2, float& c3,
                                         uint32_t a0, uint32_t a1, uint32_t a2, uint32_t a3,
                                         uint32_t b0, uint32_t b1)
{
    asm volatile(
        "mma.sync.aligned.m16n8k8.row.col.f32.tf32.tf32.f32 "
        "{%0,%1,%2,%3},{%4,%5,%6,%7},{%8,%9},{%0,%1,%2,%3};"
        : "+f"(c0), "+f"(c1), "+f"(c2), "+f"(c3)
        : "r"(a0), "r"(a1), "r"(a2), "r"(a3), "r"(b0), "r"(b1));
}

__device__ __forceinline__ void lif_elem(float v, float i, float rho, float couple,
                                         float& z_out, float& v_out, float& rho_out)
{
    float dv    = DT_TAU_MEM * ((0.0f - v) + i);
    float v_dec = (v + dv) + couple;
    float z     = (v_dec - V_TH_C) > 0.0f ? 1.0f : 0.0f;
    float v_new = (1.0f - z) * v_dec;
    float mask  = rho > 0.0f ? 1.0f : 0.0f;
    v_new = (1.0f - mask) * v_new + mask * v;
    z     = (1.0f - mask) * z;
    rho_out = (1.0f - z) * fmaxf(rho - mask, 0.0f) + z * RHO_RST;
    z_out = z;
    v_out = v_new;
}

// ---------------- role 0: packed-fp32 coupling GEMM, XOR(k&8) swizzle --------
__device__ void coupling_simt(
    char* smem_raw, int bx, int by,
    const float* __restrict__ A0, const float* __restrict__ W0,
    const float* __restrict__ vin, const float* __restrict__ iin,
    const float* __restrict__ rhoin,
    float* __restrict__ out_z, float* __restrict__ out_v, float* __restrict__ out_rho)
{
    float* As = (float*)smem_raw;                 // [BK][AST], col XOR (k&8)
    float* Bs = As + BK * AST;

    const int tid = threadIdx.x;
    const int tx = tid & 15;
    const int ty = tid >> 4;
    const int cA = tx * 4;
    const int cB = 64 + tx * 4;

    const int loadRow = tid >> 2;
    const int loadK   = (tid & 3) << 2;
    const int xs      = loadK & 8;               // store-side XOR (const per thread)
    const int sCol0   = loadRow ^ xs;            // swizzled store cols
    const int sCol1   = sCol0 + 64;

    unsigned long long acc2[4][8];
#pragma unroll
    for (int a = 0; a < 4; ++a)
#pragma unroll
        for (int b = 0; b < 8; ++b) acc2[a][b] = 0ull;

    const float* aPtr = A0 + (size_t)(by * BM + loadRow) * Kd + loadK;
    const float* wPtr = W0 + (size_t)(bx * BN + loadRow) * Kd + loadK;

    float4 ra0 = *(const float4*)(aPtr);
    float4 ra1 = *(const float4*)(aPtr + (size_t)64 * Kd);
    float4 rb0 = *(const float4*)(wPtr);
    float4 rb1 = *(const float4*)(wPtr + (size_t)64 * Kd);

    for (int kt = 0; kt < Kd; kt += BK) {
        __syncthreads();
        As[(loadK + 0) * AST + sCol0] = ra0.x;
        As[(loadK + 1) * AST + sCol0] = ra0.y;
        As[(loadK + 2) * AST + sCol0] = ra0.z;
        As[(loadK + 3) * AST + sCol0] = ra0.w;
        As[(loadK + 0) * AST + sCol1] = ra1.x;
        As[(loadK + 1) * AST + sCol1] = ra1.y;
        As[(loadK + 2) * AST + sCol1] = ra1.z;
        As[(loadK + 3) * AST + sCol1] = ra1.w;
        Bs[(loadK + 0) * AST + sCol0] = rb0.x;
        Bs[(loadK + 1) * AST + sCol0] = rb0.y;
        Bs[(loadK + 2) * AST + sCol0] = rb0.z;
        Bs[(loadK + 3) * AST + sCol0] = rb0.w;
        Bs[(loadK + 0) * AST + sCol1] = rb1.x;
        Bs[(loadK + 1) * AST + sCol1] = rb1.y;
        Bs[(loadK + 2) * AST + sCol1] = rb1.z;
        Bs[(loadK + 3) * AST + sCol1] = rb1.w;
        __syncthreads();

        if (kt + BK < Kd) {
            aPtr += BK; wPtr += BK;
            ra0 = *(const float4*)(aPtr);
            ra1 = *(const float4*)(aPtr + (size_t)64 * Kd);
            rb0 = *(const float4*)(wPtr);
            rb1 = *(const float4*)(wPtr + (size_t)64 * Kd);
        }

#pragma unroll
        for (int k = 0; k < BK; ++k) {
            const int xk = k & 8;                 // load-side XOR (uniform per k)
            float4 a0 = *(const float4*)&As[k * AST + ((ty * 8) ^ xk)];
            float4 a1 = *(const float4*)&As[k * AST + (((ty * 8) ^ xk) + 4)];
            float4 b0 = *(const float4*)&Bs[k * AST + (cA ^ xk)];
            float4 b1 = *(const float4*)&Bs[k * AST + (64 + ((cA) ^ xk))];

            unsigned long long ap[4];
            ap[0] = packf2(a0.x, a0.y);
            ap[1] = packf2(a0.z, a0.w);
            ap[2] = packf2(a1.x, a1.y);
            ap[3] = packf2(a1.z, a1.w);

            float bf[8] = {b0.x, b0.y, b0.z, b0.w, b1.x, b1.y, b1.z, b1.w};
#pragma unroll
            for (int b = 0; b < 8; ++b) {
                unsigned long long bb = dupf2(bf[b]);
                ffma2(acc2[0][b], ap[0], bb);
                ffma2(acc2[1][b], ap[1], bb);
                ffma2(acc2[2][b], ap[2], bb);
                ffma2(acc2[3][b], ap[3], bb);
            }
        }
    }

    float acc[8][8];
#pragma unroll
    for (int p = 0; p < 4; ++p)
#pragma unroll
        for (int b = 0; b < 8; ++b)
            unpackf2(acc2[p][b], acc[2 * p][b], acc[2 * p + 1][b]);

    const int row0 = by * BM + ty * 8;
    const int colA = bx * BN + cA;
    const int colB = bx * BN + cB;
#pragma unroll
    for (int a = 0; a < 8; ++a) {
#pragma unroll
        for (int h = 0; h < 2; ++h) {
            const size_t base = (size_t)(row0 + a) * Hd + (h ? colB : colA);
            const int boff = h * 4;
            float4 vv = *(const float4*)(vin + base);
            float4 iv = *(const float4*)(iin + base);
            float4 rv = *(const float4*)(rhoin + base);
            float4 oz, ov, orh;
            lif_elem(vv.x, iv.x, rv.x, acc[a][boff + 0], oz.x, ov.x, orh.x);
            lif_elem(vv.y, iv.y, rv.y, acc[a][boff + 1], oz.y, ov.y, orh.y);
            lif_elem(vv.z, iv.z, rv.z, acc[a][boff + 2], oz.z, ov.z, orh.z);
            lif_elem(vv.w, iv.w, rv.w, acc[a][boff + 3], oz.w, ov.w, orh.w);
            *(float4*)(out_z   + base) = oz;
            *(float4*)(out_v   + base) = ov;
            *(float4*)(out_rho + base) = orh;
        }
    }
}

// ---------------- role 1: TF32 MMA i-path, conflict-free position map ---------
// pos(k) = 2*f(a,c) + b, a=k>>3, b=(k>>2)&1, c=k&3; f0=[0,2,1,3], f1=[5,7,4,6].
// Fragment (ks,q): words {2f(ks,q), +1} = k {8ks+q, 8ks+q+4} -> one LDS.64.
__device__ void ipath_mma(
    char* smem_raw, int bx, int by,
    const float* __restrict__ A0, const float* __restrict__ W0,
    const float* __restrict__ A1, const float* __restrict__ W1,
    const float* __restrict__ iin, float* __restrict__ out_i)
{
    uint32_t* Ahi = (uint32_t*)smem_raw;
    uint32_t* Bhi = Ahi + BM * SSTR;

    const int tid  = threadIdx.x;
    const int warp = tid >> 5;
    const int lane = tid & 31;
    const int g    = lane >> 2;
    const int q    = lane & 3;
    const int wM   = warp >> 2;
    const int wN   = warp & 3;

    const int loadRow = tid >> 2;
    const int loadK   = (tid & 3) << 2;
    const int t       = tid & 3;
    const int ta_     = t >> 1;                   // a of this loader
    const int tb_     = t & 1;                    // b of this loader

    // store positions for c = 0..3 (see f tables)
    const int d0 = (ta_ ? 10 : 0) + tb_;
    const int d1 = (ta_ ? 14 : 4) + tb_;
    const int d2 = (ta_ ?  8 : 2) + tb_;
    const int d3 = (ta_ ? 12 : 6) + tb_;

    // fragment word offsets: ks=0 -> B0q, ks=1 -> 8 + (B0q ^ 2)
    const int B0q  = ((q & 1) << 2) | (q & 2);
    const int off0 = B0q;
    const int off1 = 8 + (B0q ^ 2);

    float acc[4][4][4];
#pragma unroll
    for (int mt = 0; mt < 4; ++mt)
#pragma unroll
        for (int nt = 0; nt < 4; ++nt)
#pragma unroll
            for (int r = 0; r < 4; ++r) acc[mt][nt][r] = 0.0f;

#pragma unroll
    for (int p = 0; p < 2; ++p) {
        const float* Amat = (p == 0) ? A0 : A1;
        const float* Wmat = (p == 0) ? W0 : W1;
        const float* aPtr = Amat + (size_t)(by * BM + loadRow) * Kd + loadK;
        const float* wPtr = Wmat + (size_t)(bx * BN + loadRow) * Kd + loadK;

        uint4 ra0 = *(const uint4*)(aPtr);
        uint4 ra1 = *(const uint4*)(aPtr + (size_t)64 * Kd);
        uint4 rb0 = *(const uint4*)(wPtr);
        uint4 rb1 = *(const uint4*)(wPtr + (size_t)64 * Kd);

        for (int kt = 0; kt < Kd; kt += BK) {
            __syncthreads();
            {
                int r0 = loadRow * SSTR;
                int r1 = (loadRow + 64) * SSTR;
                Ahi[r0 + d0] = ra0.x;
                Ahi[r0 + d1] = ra0.y;
                Ahi[r0 + d2] = ra0.z;
                Ahi[r0 + d3] = ra0.w;
                Ahi[r1 + d0] = ra1.x;
                Ahi[r1 + d1] = ra1.y;
                Ahi[r1 + d2] = ra1.z;
                Ahi[r1 + d3] = ra1.w;
                Bhi[r0 + d0] = rb0.x;
                Bhi[r0 + d1] = rb0.y;
                Bhi[r0 + d2] = rb0.z;
                Bhi[r0 + d3] = rb0.w;
                Bhi[r1 + d0] = rb1.x;
                Bhi[r1 + d1] = rb1.y;
                Bhi[r1 + d2] = rb1.z;
                Bhi[r1 + d3] = rb1.w;
            }
            __syncthreads();

            if (kt + BK < Kd) {
                aPtr += BK; wPtr += BK;
                ra0 = *(const uint4*)(aPtr);
                ra1 = *(const uint4*)(aPtr + (size_t)64 * Kd);
                rb0 = *(const uint4*)(wPtr);
                rb1 = *(const uint4*)(wPtr + (size_t)64 * Kd);
            }

#pragma unroll
            for (int ks = 0; ks < 2; ++ks) {
                const int kb = ks ? off1 : off0;
                uint32_t bh[4][2];
#pragma unroll
                for (int nt = 0; nt < 4; ++nt) {
                    int bidx = (wN * 32 + nt * 8 + g) * SSTR + kb;
                    uint2 tB = *(const uint2*)&Bhi[bidx];
                    bh[nt][0] = tB.x; bh[nt][1] = tB.y;
                }
#pragma unroll
                for (int mt = 0; mt < 4; ++mt) {
                    int r0 = (wM * 64 + mt * 16 + g) * SSTR + kb;
                    int r1 = r0 + 8 * SSTR;
                    uint2 tA = *(const uint2*)&Ahi[r0];
                    uint2 tC = *(const uint2*)&Ahi[r1];
#pragma unroll
                    for (int nt = 0; nt < 4; ++nt) {
                        float* c = acc[mt][nt];
                        mma_tf32(c[0], c[1], c[2], c[3],
                                 tA.x, tC.x, tA.y, tC.y, bh[nt][0], bh[nt][1]);
                    }
                }
            }
        }
    }

#pragma unroll
    for (int mt = 0; mt < 4; ++mt) {
#pragma unroll
        for (int nt = 0; nt < 4; ++nt) {
            const float* c = acc[mt][nt];
            int row0 = by * BM + wM * 64 + mt * 16 + g;
            int col  = bx * BN + wN * 32 + nt * 8 + 2 * q;
            size_t idx0 = (size_t)row0 * Hd + col;
            size_t idx1 = idx0 + (size_t)8 * Hd;
            float2 i0 = *(const float2*)(iin + idx0);
            float2 i1 = *(const float2*)(iin + idx1);
            float2 o0, o1;
            o0.x = (i0.x - DT_TAU_SYN * i0.x) + c[0];
            o0.y = (i0.y - DT_TAU_SYN * i0.y) + c[1];
            o1.x = (i1.x - DT_TAU_SYN * i1.x) + c[2];
            o1.y = (i1.y - DT_TAU_SYN * i1.y) + c[3];
            *(float2*)(out_i + idx0) = o0;
            *(float2*)(out_i + idx1) = o1;
        }
    }
}

__global__ void __launch_bounds__(NTHREADS, 2) lif_hybrid_kernel(
    const float* __restrict__ inp, const float* __restrict__ z,
    const float* __restrict__ v,   const float* __restrict__ icur,
    const float* __restrict__ rho,
    const float* __restrict__ Wi,  const float* __restrict__ Wr,
    const float* __restrict__ g,
    float* __restrict__ out_z, float* __restrict__ out_v,
    float* __restrict__ out_i, float* __restrict__ out_rho)
{
    __shared__ __align__(16) char smem_raw[SMEM_BYTES_MAX];

    const int bid  = blockIdx.x;
    const int role = (bid >> 2) & 1;     // co-resident CTAs mix roles
    const int sub  = (bid >> 3) * 4 + (bid & 3);
    const int bx = sub & 15;
    const int by = sub >> 4;

    if (role == 0) {
        coupling_simt(smem_raw, bx, by, v, g, v, icur, rho, out_z, out_v, out_rho);
    } else {
        ipath_mma(smem_raw, bx, by, inp, Wi, z, Wr, icur, out_i);
    }
}

extern "C" void kernel_launch(void* const* d_in, const int* in_sizes, int n_in,
                              void* d_out, int out_size)
{
    const float* inp  = (const float*)d_in[0];
    const float* z    = (const float*)d_in[1];
    const float* v    = (const float*)d_in[2];
    const float* icur = (const float*)d_in[3];
    const float* rho  = (const float*)d_in[4];
    const float* Wi   = (const float*)d_in[5];
    const float* Wr   = (const float*)d_in[6];
    const float* g    = (const float*)d_in[7];

    float* out      = (float*)d_out;
    const size_t nBH = (size_t)Bd * Hd;

    lif_hybrid_kernel<<<1024, NTHREADS>>>(
        inp, z, v, icur, rho, Wi, Wr, g,
        out, out + nBH, out + 2 * nBH, out + 3 * nBH);
}